// round 2
// baseline (speedup 1.0000x reference)
#include <cuda_runtime.h>

// Autoregressive 2-layer LSTM decoder, B=256, T=512, H=256, F=1.
// Design: persistent kernel, 64 CTAs x 256 threads, each CTA owns 4 batch
// elements for the full 512-step recurrence (batch elements are independent,
// so no grid sync is ever needed). Weights are pre-transposed into
// k-pair-major, gate-interleaved float4 tiles so thread j's loads are fully
// coalesced LDG.128 and each weight load is reused across 4 batch elements
// in registers. Inner products use packed fma.rn.f32x2 (FFMA2).
//
// Input order (metadata): 0 sequence(B,T,F) 1 z(B,H) 2 lengths 3 W_ih_l0
// 4 W_hh_l0 5 b_ih_l0 6 b_hh_l0 7 W_ih_l1 8 W_hh_l1 9 b_ih_l1 10 b_hh_l1
// 11 W_out 12 b_out.  Output: scalar fp32 loss.

#define HDIM   256
#define TSTEPS 512
#define BTOT   256
#define BC     4
#define NCTA   (BTOT / BC)
#define NTHR   256

// Pre-transformed weights (device scratch; allocation-free rule -> __device__ globals)
// A0[kp*256+j] = {Wi[j][2kp], Wi[j][2kp+1], Wf[j][2kp], Wf[j][2kp+1]} of W_hh_l0
// B0           = same for gates g,o
// A1/B1: layer-1 concatenated K: kp<128 -> W_ih_l1 (input = h0_new),
//        kp>=128 -> W_hh_l1 (input = h1_prev)
__device__ float4 A0g[128 * 256];
__device__ float4 B0g[128 * 256];
__device__ float4 A1g[256 * 256];
__device__ float4 B1g[256 * 256];

__global__ void zero_out_kernel(float* o) { o[0] = 0.0f; }

__global__ void prep_kernel(const float* __restrict__ Whh0,
                            const float* __restrict__ Wih1,
                            const float* __restrict__ Whh1) {
    int idx = blockIdx.x * blockDim.x + threadIdx.x;  // 0 .. 384*256
    int j = idx & 255;
    if (idx < 128 * 256) {
        int kp = idx >> 8;
        int k  = kp << 1;
        A0g[idx] = make_float4(Whh0[(j      ) * HDIM + k], Whh0[(j      ) * HDIM + k + 1],
                               Whh0[(256 + j) * HDIM + k], Whh0[(256 + j) * HDIM + k + 1]);
        B0g[idx] = make_float4(Whh0[(512 + j) * HDIM + k], Whh0[(512 + j) * HDIM + k + 1],
                               Whh0[(768 + j) * HDIM + k], Whh0[(768 + j) * HDIM + k + 1]);
    } else {
        int i2 = idx - 128 * 256;
        int kp = i2 >> 8;
        const float* src = (kp < 128) ? Wih1 : Whh1;
        int k = (kp < 128) ? (kp << 1) : ((kp - 128) << 1);
        A1g[i2] = make_float4(src[(j      ) * HDIM + k], src[(j      ) * HDIM + k + 1],
                              src[(256 + j) * HDIM + k], src[(256 + j) * HDIM + k + 1]);
        B1g[i2] = make_float4(src[(512 + j) * HDIM + k], src[(512 + j) * HDIM + k + 1],
                              src[(768 + j) * HDIM + k], src[(768 + j) * HDIM + k + 1]);
    }
}

// ---- packed f32x2 helpers ----
__device__ __forceinline__ unsigned long long pk2(float x, float y) {
    unsigned long long r;
    asm("mov.b64 %0, {%1, %2};" : "=l"(r) : "f"(x), "f"(y));
    return r;
}
__device__ __forceinline__ void ffma2(unsigned long long& d, unsigned long long a,
                                      unsigned long long b) {
    asm("fma.rn.f32x2 %0, %1, %2, %0;" : "+l"(d) : "l"(a), "l"(b));
}
__device__ __forceinline__ float sum2(unsigned long long v) {
    float x, y;
    asm("mov.b64 {%0, %1}, %2;" : "=f"(x), "=f"(y) : "l"(v));
    return x + y;
}

__device__ __forceinline__ float sigf(float x) {
    return 1.0f / (1.0f + __expf(-x));
}
__device__ __forceinline__ float tanh_f(float x) {
    // exact at both saturations: x->+inf: 1-0, x->-inf: 1-2 = -1
    return 1.0f - 2.0f / (__expf(2.0f * x) + 1.0f);
}

__global__ void __launch_bounds__(NTHR, 1)
lstm_decoder_kernel(const float* __restrict__ seq,   // (B,T,1)
                    const float* __restrict__ z,     // (B,H)
                    const float* __restrict__ wih0,  // (4H,1)
                    const float* __restrict__ bih0, const float* __restrict__ bhh0,
                    const float* __restrict__ bih1, const float* __restrict__ bhh1,
                    const float* __restrict__ wout,  // (1,H)
                    const float* __restrict__ bout,  // (1,)
                    float* out) {
    __shared__ float h0s[2][BC][HDIM];   // ping-pong layer-0 hidden
    __shared__ float h1s[2][BC][HDIM];   // ping-pong layer-1 hidden
    __shared__ float pred_s[BC];
    __shared__ float wout_s[HDIM];

    const int j  = threadIdx.x;          // owned hidden index
    const int b0 = blockIdx.x * BC;      // first batch element of this CTA
    const int w  = j >> 5, l = j & 31;

    float c0r[BC], c1r[BC];
#pragma unroll
    for (int b = 0; b < BC; b++) {
        float zz = z[(b0 + b) * HDIM + j];
        h0s[0][b][j] = zz;
        h1s[0][b][j] = zz;
        c0r[b] = zz;
        c1r[b] = zz;
    }
    if (j < BC) pred_s[j] = 0.0f;
    wout_s[j] = wout[j];

    // loop-invariant biases and scalar-input weights
    const float bi0 = bih0[j]       + bhh0[j];
    const float bf0 = bih0[256 + j] + bhh0[256 + j];
    const float bg0 = bih0[512 + j] + bhh0[512 + j];
    const float bo0 = bih0[768 + j] + bhh0[768 + j];
    const float bi1 = bih1[j]       + bhh1[j];
    const float bf1 = bih1[256 + j] + bhh1[256 + j];
    const float bg1 = bih1[512 + j] + bhh1[512 + j];
    const float bo1 = bih1[768 + j] + bhh1[768 + j];
    const float wii = wih0[j], wif = wih0[256 + j], wig = wih0[512 + j], wio = wih0[768 + j];
    const float bo_out = bout[0];

    float loss = 0.0f;
    __syncthreads();

    for (int t = 0; t < TSTEPS; t++) {
        const int cur = t & 1, nxt = cur ^ 1;

        // ================= layer 0: gates = Whh0 @ h0 (+ pred*wih0 + bias) ======
        unsigned long long ai[BC], af[BC], ag[BC], ao[BC];
#pragma unroll
        for (int b = 0; b < BC; b++) { ai[b] = 0ull; af[b] = 0ull; ag[b] = 0ull; ao[b] = 0ull; }

#pragma unroll 4
        for (int kp = 0; kp < 128; kp++) {
            float4 a = A0g[(kp << 8) + j];
            float4 q = B0g[(kp << 8) + j];
            unsigned long long axy = pk2(a.x, a.y), azw = pk2(a.z, a.w);
            unsigned long long qxy = pk2(q.x, q.y), qzw = pk2(q.z, q.w);
#pragma unroll
            for (int b = 0; b < BC; b++) {
                unsigned long long h =
                    *reinterpret_cast<const unsigned long long*>(&h0s[cur][b][kp << 1]);
                ffma2(ai[b], axy, h);
                ffma2(af[b], azw, h);
                ffma2(ag[b], qxy, h);
                ffma2(ao[b], qzw, h);
            }
        }
#pragma unroll
        for (int b = 0; b < BC; b++) {
            float p  = pred_s[b];
            float gi = sum2(ai[b]) + bi0 + p * wii;
            float gf = sum2(af[b]) + bf0 + p * wif;
            float gg = sum2(ag[b]) + bg0 + p * wig;
            float go = sum2(ao[b]) + bo0 + p * wio;
            float cn = sigf(gf) * c0r[b] + sigf(gi) * tanh_f(gg);
            c0r[b] = cn;
            h0s[nxt][b][j] = sigf(go) * tanh_f(cn);
        }
        __syncthreads();

        // ========= layer 1: gates = Wih1 @ h0_new + Whh1 @ h1 (+ bias) ==========
#pragma unroll
        for (int b = 0; b < BC; b++) { ai[b] = 0ull; af[b] = 0ull; ag[b] = 0ull; ao[b] = 0ull; }

#pragma unroll 4
        for (int kp = 0; kp < 128; kp++) {  // K-part 1: h0_new through Wih1
            float4 a = A1g[(kp << 8) + j];
            float4 q = B1g[(kp << 8) + j];
            unsigned long long axy = pk2(a.x, a.y), azw = pk2(a.z, a.w);
            unsigned long long qxy = pk2(q.x, q.y), qzw = pk2(q.z, q.w);
#pragma unroll
            for (int b = 0; b < BC; b++) {
                unsigned long long h =
                    *reinterpret_cast<const unsigned long long*>(&h0s[nxt][b][kp << 1]);
                ffma2(ai[b], axy, h);
                ffma2(af[b], azw, h);
                ffma2(ag[b], qxy, h);
                ffma2(ao[b], qzw, h);
            }
        }
#pragma unroll 4
        for (int kp = 0; kp < 128; kp++) {  // K-part 2: h1_prev through Whh1
            float4 a = A1g[((kp + 128) << 8) + j];
            float4 q = B1g[((kp + 128) << 8) + j];
            unsigned long long axy = pk2(a.x, a.y), azw = pk2(a.z, a.w);
            unsigned long long qxy = pk2(q.x, q.y), qzw = pk2(q.z, q.w);
#pragma unroll
            for (int b = 0; b < BC; b++) {
                unsigned long long h =
                    *reinterpret_cast<const unsigned long long*>(&h1s[cur][b][kp << 1]);
                ffma2(ai[b], axy, h);
                ffma2(af[b], azw, h);
                ffma2(ag[b], qxy, h);
                ffma2(ao[b], qzw, h);
            }
        }
#pragma unroll
        for (int b = 0; b < BC; b++) {
            float gi = sum2(ai[b]) + bi1;
            float gf = sum2(af[b]) + bf1;
            float gg = sum2(ag[b]) + bg1;
            float go = sum2(ao[b]) + bo1;
            float cn = sigf(gf) * c1r[b] + sigf(gi) * tanh_f(gg);
            c1r[b] = cn;
            h1s[nxt][b][j] = sigf(go) * tanh_f(cn);
        }
        __syncthreads();

        // ============== output projection + loss, one warp per batch elem =======
        if (w < BC) {
            float s = 0.0f;
#pragma unroll
            for (int m = 0; m < 8; m++) {
                int jj = l + (m << 5);
                s += wout_s[jj] * h1s[nxt][w][jj];
            }
#pragma unroll
            for (int off = 16; off; off >>= 1) s += __shfl_xor_sync(0xffffffffu, s, off);
            if (l == 0) {
                float p = s + bo_out;
                pred_s[w] = p;
                float d = seq[(b0 + w) * TSTEPS + t] - p;
                loss += d * d;
            }
        }
        __syncthreads();
    }

    if (w < BC && l == 0) {
        atomicAdd(out, loss * (1.0f / ((float)BTOT * (float)TSTEPS)));
    }
}

extern "C" void kernel_launch(void* const* d_in, const int* in_sizes, int n_in,
                              void* d_out, int out_size) {
    const float* seq  = (const float*)d_in[0];
    const float* z    = (const float*)d_in[1];
    // d_in[2] = lengths (all == T, unused by the reference math)
    const float* wih0 = (const float*)d_in[3];
    const float* whh0 = (const float*)d_in[4];
    const float* bih0 = (const float*)d_in[5];
    const float* bhh0 = (const float*)d_in[6];
    const float* wih1 = (const float*)d_in[7];
    const float* whh1 = (const float*)d_in[8];
    const float* bih1 = (const float*)d_in[9];
    const float* bhh1 = (const float*)d_in[10];
    const float* wout = (const float*)d_in[11];
    const float* bout = (const float*)d_in[12];
    float* out = (float*)d_out;

    zero_out_kernel<<<1, 1>>>(out);
    prep_kernel<<<384, 256>>>(whh0, wih1, whh1);
    lstm_decoder_kernel<<<NCTA, NTHR>>>(seq, z, wih0, bih0, bhh0,
                                        bih1, bhh1, wout, bout, out);
}

// round 9
// speedup vs baseline: 1.9886x; 1.9886x over previous
#include <cuda_runtime.h>
#include <cuda_bf16.h>
#include <cstdint>

// Autoregressive 2-layer LSTM decoder, B=256, T=512, H=256, F=1.
//
// Design (7th submission of the R3 design; R3-R8 benches all hit
// GPUAcquisitionTimeout and never ran -- audited four times: sync
// semantics, launch path, numerics, graph-capture. Unchanged):
//  * 128 CTAs as 64 clusters of 2 (cluster dim (2,1,1)) -> 128 SMs busy.
//  * Each cluster owns 4 batch elements; CTA rank r owns hidden slice
//    j in [128r, 128r+128). Threads: tid = kh*128 + jl; kh = K-half,
//    jl = local hidden index. Each (jl) pair of threads splits the K
//    reduction; partials combined through SMEM.
//  * Weights pre-packed to bf16 in __device__ globals, gate-interleaved:
//    one LDG.128 per (thread, k-pair) carries all 4 gates x 2 k values.
//    L2 weight traffic: 96 MB/step (was 192 MB fp32).
//  * h state fp32 in SMEM, k-pair-major with batch-interleaved rows so
//    one LDS.128 broadcast feeds 2 batches' f32x2 pairs.
//  * h halves exchanged across the cluster with st.shared::cluster (mapa)
//    + barrier.cluster (2 per step). All gate math fp32 (fma.rn.f32x2).
//  * Loss zeroing folded into prep_kernel (2 launches per call) so
//    ncu -s 5 -c 1 lands on the main kernel.

#define HDIM   256
#define TSTEPS 512
#define BTOT   256
#define BC     4
#define NTHR   256
#define NCTA   128   // 64 clusters * 2

// Packed bf16 weights: [rank][kp][tid] of uint4 (8 bf16 = 4 gates x 2 k)
__device__ uint4 L0p[2 * 64 * 256];    // layer0: per-thread K-range 128 -> 64 kp
__device__ uint4 L1p[2 * 128 * 256];   // layer1: per-thread K-range 256 -> 128 kp

__device__ __forceinline__ uint32_t pack_bf2(float lo, float hi) {
    __nv_bfloat162 t = __floats2bfloat162_rn(lo, hi);
    return *reinterpret_cast<uint32_t*>(&t);
}

__global__ void prep_kernel(const float* __restrict__ Whh0,
                            const float* __restrict__ Wih1,
                            const float* __restrict__ Whh1,
                            float* out) {
    int idx = blockIdx.x * blockDim.x + threadIdx.x;
    if (idx == 0) out[0] = 0.0f;   // loss accumulator zeroing
    const int L0N = 2 * 64 * 256;
    const int L1N = 2 * 128 * 256;
    if (idx < L0N) {
        int rank = idx / (64 * 256);
        int rem  = idx % (64 * 256);
        int kp   = rem >> 8;
        int tid  = rem & 255;
        int kh = tid >> 7, jl = tid & 127;
        int j = rank * 128 + jl;
        int k = kh * 128 + kp * 2;
        uint4 v;
        v.x = pack_bf2(Whh0[(0 * 256 + j) * HDIM + k], Whh0[(0 * 256 + j) * HDIM + k + 1]);
        v.y = pack_bf2(Whh0[(1 * 256 + j) * HDIM + k], Whh0[(1 * 256 + j) * HDIM + k + 1]);
        v.z = pack_bf2(Whh0[(2 * 256 + j) * HDIM + k], Whh0[(2 * 256 + j) * HDIM + k + 1]);
        v.w = pack_bf2(Whh0[(3 * 256 + j) * HDIM + k], Whh0[(3 * 256 + j) * HDIM + k + 1]);
        L0p[idx] = v;
    } else if (idx < L0N + L1N) {
        int i2   = idx - L0N;
        int rank = i2 / (128 * 256);
        int rem  = i2 % (128 * 256);
        int kp   = rem >> 8;
        int tid  = rem & 255;
        int kh = tid >> 7, jl = tid & 127;
        int j = rank * 128 + jl;
        int k = kp * 2;
        const float* src = kh ? Whh1 : Wih1;  // kh0: K=h0_new via Wih1; kh1: K=h1 via Whh1
        uint4 v;
        v.x = pack_bf2(src[(0 * 256 + j) * HDIM + k], src[(0 * 256 + j) * HDIM + k + 1]);
        v.y = pack_bf2(src[(1 * 256 + j) * HDIM + k], src[(1 * 256 + j) * HDIM + k + 1]);
        v.z = pack_bf2(src[(2 * 256 + j) * HDIM + k], src[(2 * 256 + j) * HDIM + k + 1]);
        v.w = pack_bf2(src[(3 * 256 + j) * HDIM + k], src[(3 * 256 + j) * HDIM + k + 1]);
        L1p[i2] = v;
    }
}

// ---------- device helpers ----------
typedef unsigned long long u64;

__device__ __forceinline__ uint32_t s2u(const void* p) {
    return (uint32_t)__cvta_generic_to_shared(p);
}
// bf16x2 word -> f32x2 (64-bit reg pair) via 2 PRMT (alu pipe)
__device__ __forceinline__ u64 bf2f2(uint32_t w) {
    uint32_t lo, hi;
    asm("prmt.b32 %0, %1, %2, 0x1044;" : "=r"(lo) : "r"(w), "r"(0u));
    asm("prmt.b32 %0, %1, %2, 0x3244;" : "=r"(hi) : "r"(w), "r"(0u));
    u64 r;
    asm("mov.b64 %0, {%1,%2};" : "=l"(r) : "r"(lo), "r"(hi));
    return r;
}
__device__ __forceinline__ void ffma2(u64& d, u64 a, u64 b) {
    asm("fma.rn.f32x2 %0, %1, %2, %0;" : "+l"(d) : "l"(a), "l"(b));
}
__device__ __forceinline__ float sum2(u64 v) {
    float x, y;
    asm("mov.b64 {%0, %1}, %2;" : "=f"(x), "=f"(y) : "l"(v));
    return x + y;
}
__device__ __forceinline__ void lds2x64(u64& a, u64& b, uint32_t addr) {
    asm volatile("ld.shared.v2.u64 {%0,%1}, [%2];" : "=l"(a), "=l"(b) : "r"(addr));
}
__device__ __forceinline__ void st_peer_f32(uint32_t addr, uint32_t peer, float v) {
    uint32_t ra;
    asm("mapa.shared::cluster.u32 %0, %1, %2;" : "=r"(ra) : "r"(addr), "r"(peer));
    asm volatile("st.shared::cluster.f32 [%0], %1;" :: "r"(ra), "f"(v) : "memory");
}
__device__ __forceinline__ void cluster_sync_() {
    asm volatile("barrier.cluster.arrive.aligned;" ::: "memory");
    asm volatile("barrier.cluster.wait.aligned;" ::: "memory");
}
__device__ __forceinline__ float sigf(float x) { return 1.0f / (1.0f + __expf(-x)); }
__device__ __forceinline__ float tanh_f(float x) {
    return 1.0f - 2.0f / (__expf(2.0f * x) + 1.0f);
}

// h storage: per kp-row of 32 bytes: [b0k0,b0k1,b1k0,b1k1,b2k0,b2k1,b3k0,b3k1]
// element (j, b) lives at [(j>>1)*8 + b*2 + (j&1)]
__device__ __forceinline__ int hidx(int j, int b) {
    return ((j >> 1) << 3) + (b << 1) + (j & 1);
}

__global__ void __launch_bounds__(NTHR, 1) __cluster_dims__(2, 1, 1)
lstm_decoder_kernel(const float* __restrict__ seq,   // (B,T,1)
                    const float* __restrict__ z,     // (B,H)
                    const float* __restrict__ wih0,  // (4H,1)
                    const float* __restrict__ bih0, const float* __restrict__ bhh0,
                    const float* __restrict__ bih1, const float* __restrict__ bhh1,
                    const float* __restrict__ wout,  // (1,H)
                    const float* __restrict__ bout,  // (1,)
                    float* out) {
    __shared__ __align__(16) float hp0[2][128 * 8];   // layer0 h, ping-pong
    __shared__ __align__(16) float hp1[2][128 * 8];   // layer1 h, ping-pong
    __shared__ float part[128 * 17];                  // K-hi partials (padded)
    __shared__ float pred_s[BC];
    __shared__ float wout_s[HDIM];

    const int tid  = threadIdx.x;
    const int kh   = tid >> 7;       // K-half this thread reduces
    const int jl   = tid & 127;      // local hidden index
    const int rank = blockIdx.x & 1; // cluster CTA rank (cluster dim (2,1,1))
    const int peer = rank ^ 1;
    const int j    = rank * 128 + jl;     // global hidden index owned (kh==0 threads)
    const int b0   = (blockIdx.x >> 1) * BC;
    const int w    = tid >> 5, l = tid & 31;

    // ---- init h from z (full vectors, both halves, local smem) ----
    for (int idx = tid; idx < BC * HDIM; idx += NTHR) {
        int b = idx >> 8, jj = idx & 255;
        float v = z[(b0 + b) * HDIM + jj];
        hp0[0][hidx(jj, b)] = v;
        hp1[0][hidx(jj, b)] = v;
    }
    if (tid < BC) pred_s[tid] = 0.0f;
    wout_s[tid] = wout[tid];

    float c0[BC], c1[BC];
#pragma unroll
    for (int b = 0; b < BC; b++) {
        float v = z[(b0 + b) * HDIM + j];
        c0[b] = v;
        c1[b] = v;
    }

    // finalization constants (used by kh==0 threads)
    const float bi0 = bih0[j] + bhh0[j];
    const float bf0 = bih0[256 + j] + bhh0[256 + j];
    const float bg0 = bih0[512 + j] + bhh0[512 + j];
    const float bo0 = bih0[768 + j] + bhh0[768 + j];
    const float bi1 = bih1[j] + bhh1[j];
    const float bf1 = bih1[256 + j] + bhh1[256 + j];
    const float bg1 = bih1[512 + j] + bhh1[512 + j];
    const float bo1 = bih1[768 + j] + bhh1[768 + j];
    const float wii = wih0[j], wif = wih0[256 + j], wig = wih0[512 + j], wio = wih0[768 + j];
    const float bo_out = bout[0];
    const float inv_n  = 1.0f / ((float)BTOT * (float)TSTEPS);

    const uint4* w0 = L0p + (rank * 64) * 256 + tid;
    const uint4* w1 = L1p + (rank * 128) * 256 + tid;

    float loss = 0.0f;
    __syncthreads();

    for (int t = 0; t < TSTEPS; t++) {
        const int cur = t & 1, nxt = cur ^ 1;

        // ================= layer 0 ==================
        u64 acc[16];
#pragma unroll
        for (int q = 0; q < 16; q++) acc[q] = 0ull;
        {
            const uint32_t hbase = s2u(&hp0[cur][0]) + (kh ? 64 * 32 : 0);
#pragma unroll 8
            for (int kp = 0; kp < 64; kp++) {
                uint4 wv = w0[kp * 256];
                u64 wi2 = bf2f2(wv.x), wf2 = bf2f2(wv.y);
                u64 wg2 = bf2f2(wv.z), wo2 = bf2f2(wv.w);
                u64 h01a, h01b, h23a, h23b;
                lds2x64(h01a, h01b, hbase + kp * 32);
                lds2x64(h23a, h23b, hbase + kp * 32 + 16);
                ffma2(acc[0], wi2, h01a);  ffma2(acc[1], wf2, h01a);
                ffma2(acc[2], wg2, h01a);  ffma2(acc[3], wo2, h01a);
                ffma2(acc[4], wi2, h01b);  ffma2(acc[5], wf2, h01b);
                ffma2(acc[6], wg2, h01b);  ffma2(acc[7], wo2, h01b);
                ffma2(acc[8], wi2, h23a);  ffma2(acc[9], wf2, h23a);
                ffma2(acc[10], wg2, h23a); ffma2(acc[11], wo2, h23a);
                ffma2(acc[12], wi2, h23b); ffma2(acc[13], wf2, h23b);
                ffma2(acc[14], wg2, h23b); ffma2(acc[15], wo2, h23b);
            }
        }
        if (kh) {
#pragma unroll
            for (int q = 0; q < 16; q++) part[jl * 17 + q] = sum2(acc[q]);
        }
        __syncthreads();
        if (!kh) {
            const uint32_t hdst = s2u(&hp0[nxt][0]);
#pragma unroll
            for (int b = 0; b < BC; b++) {
                float p  = pred_s[b];
                float gi = sum2(acc[b * 4 + 0]) + part[jl * 17 + b * 4 + 0] + bi0 + p * wii;
                float gf = sum2(acc[b * 4 + 1]) + part[jl * 17 + b * 4 + 1] + bf0 + p * wif;
                float gg = sum2(acc[b * 4 + 2]) + part[jl * 17 + b * 4 + 2] + bg0 + p * wig;
                float go = sum2(acc[b * 4 + 3]) + part[jl * 17 + b * 4 + 3] + bo0 + p * wio;
                float cn = sigf(gf) * c0[b] + sigf(gi) * tanh_f(gg);
                c0[b] = cn;
                float hn = sigf(go) * tanh_f(cn);
                int idx = hidx(j, b);
                hp0[nxt][idx] = hn;
                st_peer_f32(hdst + idx * 4, peer, hn);
            }
        }
        cluster_sync_();

        // ================= layer 1 ==================
#pragma unroll
        for (int q = 0; q < 16; q++) acc[q] = 0ull;
        {
            const uint32_t hbase = kh ? s2u(&hp1[cur][0]) : s2u(&hp0[nxt][0]);
#pragma unroll 8
            for (int kp = 0; kp < 128; kp++) {
                uint4 wv = w1[kp * 256];
                u64 wi2 = bf2f2(wv.x), wf2 = bf2f2(wv.y);
                u64 wg2 = bf2f2(wv.z), wo2 = bf2f2(wv.w);
                u64 h01a, h01b, h23a, h23b;
                lds2x64(h01a, h01b, hbase + kp * 32);
                lds2x64(h23a, h23b, hbase + kp * 32 + 16);
                ffma2(acc[0], wi2, h01a);  ffma2(acc[1], wf2, h01a);
                ffma2(acc[2], wg2, h01a);  ffma2(acc[3], wo2, h01a);
                ffma2(acc[4], wi2, h01b);  ffma2(acc[5], wf2, h01b);
                ffma2(acc[6], wg2, h01b);  ffma2(acc[7], wo2, h01b);
                ffma2(acc[8], wi2, h23a);  ffma2(acc[9], wf2, h23a);
                ffma2(acc[10], wg2, h23a); ffma2(acc[11], wo2, h23a);
                ffma2(acc[12], wi2, h23b); ffma2(acc[13], wf2, h23b);
                ffma2(acc[14], wg2, h23b); ffma2(acc[15], wo2, h23b);
            }
        }
        if (kh) {
#pragma unroll
            for (int q = 0; q < 16; q++) part[jl * 17 + q] = sum2(acc[q]);
        }
        __syncthreads();
        if (!kh) {
            const uint32_t hdst = s2u(&hp1[nxt][0]);
#pragma unroll
            for (int b = 0; b < BC; b++) {
                float gi = sum2(acc[b * 4 + 0]) + part[jl * 17 + b * 4 + 0] + bi1;
                float gf = sum2(acc[b * 4 + 1]) + part[jl * 17 + b * 4 + 1] + bf1;
                float gg = sum2(acc[b * 4 + 2]) + part[jl * 17 + b * 4 + 2] + bg1;
                float go = sum2(acc[b * 4 + 3]) + part[jl * 17 + b * 4 + 3] + bo1;
                float cn = sigf(gf) * c1[b] + sigf(gi) * tanh_f(gg);
                c1[b] = cn;
                float hn = sigf(go) * tanh_f(cn);
                int idx = hidx(j, b);
                hp1[nxt][idx] = hn;
                st_peer_f32(hdst + idx * 4, peer, hn);
            }
        }
        cluster_sync_();

        // ============ output projection + loss (warp w -> batch w) ============
        if (w < BC) {
            float s = 0.0f;
#pragma unroll
            for (int m = 0; m < 8; m++) {
                int j2 = l + (m << 5);
                s += wout_s[j2] * hp1[nxt][hidx(j2, w)];
            }
#pragma unroll
            for (int off = 16; off; off >>= 1) s += __shfl_xor_sync(0xffffffffu, s, off);
            float p = s + bo_out;   // all lanes hold the reduced value
            if (l == 0) {
                pred_s[w] = p;
                if (rank == 0) {
                    float d = seq[(b0 + w) * TSTEPS + t] - p;
                    loss += d * d;
                }
            }
        }
        __syncthreads();
    }

    if (rank == 0 && w < BC && l == 0) {
        atomicAdd(out, loss * inv_n);
    }
}

extern "C" void kernel_launch(void* const* d_in, const int* in_sizes, int n_in,
                              void* d_out, int out_size) {
    const float* seq  = (const float*)d_in[0];
    const float* z    = (const float*)d_in[1];
    // d_in[2] = lengths (all == T; unused by the math)
    const float* wih0 = (const float*)d_in[3];
    const float* whh0 = (const float*)d_in[4];
    const float* bih0 = (const float*)d_in[5];
    const float* bhh0 = (const float*)d_in[6];
    const float* wih1 = (const float*)d_in[7];
    const float* whh1 = (const float*)d_in[8];
    const float* bih1 = (const float*)d_in[9];
    const float* bhh1 = (const float*)d_in[10];
    const float* wout = (const float*)d_in[11];
    const float* bout = (const float*)d_in[12];
    float* out = (float*)d_out;

    prep_kernel<<<384, 256>>>(whh0, wih1, whh1, out);
    lstm_decoder_kernel<<<NCTA, NTHR>>>(seq, z, wih0, bih0, bhh0,
                                        bih1, bhh1, wout, bout, out);
}

// round 12
// speedup vs baseline: 2.0321x; 1.0219x over previous
#include <cuda_runtime.h>
#include <cuda_bf16.h>
#include <cstdint>

// Autoregressive 2-layer LSTM decoder, B=256, T=512, H=256, F=1.
//
// R10 design, 3rd submission (R10/R11 benches hit GPUAcquisitionTimeout
// and never ran; audited, unchanged). Evolves the measured R9 kernel
// (8837us, issue=33.7%, occ=12.5%, nothing saturated -> latency-bound
// with 8 warps/SM):
//  * 128 CTAs as 64 clusters of 2; each cluster owns 4 batch elements,
//    CTA rank r owns hidden slice j in [128r,128r+128).
//  * 512 threads/CTA (16 warps/SM, occ 25%). tid = g*128 + jl,
//    g in 0..3 = K-quarter this thread reduces. Per-phase serial chain
//    halves (L0: 32 kp, L1: 64 kp); same total FFMA2 work, same 96 MB/step
//    L2 weight traffic, 2x warps to hide LDG/LDS latency.
//  * Groups 1-3 dump 16 partials each to smem (stride-49 padded,
//    conflict-free); group 0 combines + finalizes gates.
//  * Weights bf16, gate-interleaved uint4 (4 gates x 2 k per LDG.128),
//    repacked for the 4-way K split. h fp32 in SMEM (hidx rows).
//  * Cluster h-exchange via mapa + st.shared::cluster, 2 barriers/step.
//  * Unroll 4 to respect the 128-reg cap at 512 threads.

#define HDIM   256
#define TSTEPS 512
#define BTOT   256
#define BC     4
#define NTHR   512
#define NCTA   128   // 64 clusters * 2

// Packed bf16 weights, [rank][kp][tid512] of uint4 (4 gates x 2 k)
__device__ uint4 L0p[2 * 32 * 512];    // layer0: K=256 4-way -> 32 kp/thread
__device__ uint4 L1p[2 * 64 * 512];    // layer1: K=512 4-way -> 64 kp/thread

__device__ __forceinline__ uint32_t pack_bf2(float lo, float hi) {
    __nv_bfloat162 t = __floats2bfloat162_rn(lo, hi);
    return *reinterpret_cast<uint32_t*>(&t);
}

__global__ void prep_kernel(const float* __restrict__ Whh0,
                            const float* __restrict__ Wih1,
                            const float* __restrict__ Whh1,
                            float* out) {
    int idx = blockIdx.x * blockDim.x + threadIdx.x;
    if (idx == 0) out[0] = 0.0f;   // loss accumulator zeroing
    const int L0N = 2 * 32 * 512;
    const int L1N = 2 * 64 * 512;
    if (idx < L0N) {
        int rank = idx / (32 * 512);
        int rem  = idx % (32 * 512);
        int kp   = rem >> 9;
        int tid  = rem & 511;
        int g = tid >> 7, jl = tid & 127;
        int j = rank * 128 + jl;
        int k = g * 64 + kp * 2;
        uint4 v;
        v.x = pack_bf2(Whh0[(0 * 256 + j) * HDIM + k], Whh0[(0 * 256 + j) * HDIM + k + 1]);
        v.y = pack_bf2(Whh0[(1 * 256 + j) * HDIM + k], Whh0[(1 * 256 + j) * HDIM + k + 1]);
        v.z = pack_bf2(Whh0[(2 * 256 + j) * HDIM + k], Whh0[(2 * 256 + j) * HDIM + k + 1]);
        v.w = pack_bf2(Whh0[(3 * 256 + j) * HDIM + k], Whh0[(3 * 256 + j) * HDIM + k + 1]);
        L0p[idx] = v;
    } else if (idx < L0N + L1N) {
        int i2   = idx - L0N;
        int rank = i2 / (64 * 512);
        int rem  = i2 % (64 * 512);
        int kp   = rem >> 9;
        int tid  = rem & 511;
        int g = tid >> 7, jl = tid & 127;
        int j = rank * 128 + jl;
        // g0,g1: K = h0_new via Wih1 (k = g*128 + 2kp)
        // g2,g3: K = h1_prev via Whh1 (k = (g-2)*128 + 2kp)
        const float* src = (g < 2) ? Wih1 : Whh1;
        int k = ((g & 1) * 128) + kp * 2;
        uint4 v;
        v.x = pack_bf2(src[(0 * 256 + j) * HDIM + k], src[(0 * 256 + j) * HDIM + k + 1]);
        v.y = pack_bf2(src[(1 * 256 + j) * HDIM + k], src[(1 * 256 + j) * HDIM + k + 1]);
        v.z = pack_bf2(src[(2 * 256 + j) * HDIM + k], src[(2 * 256 + j) * HDIM + k + 1]);
        v.w = pack_bf2(src[(3 * 256 + j) * HDIM + k], src[(3 * 256 + j) * HDIM + k + 1]);
        L1p[i2] = v;
    }
}

// ---------- device helpers ----------
typedef unsigned long long u64;

__device__ __forceinline__ uint32_t s2u(const void* p) {
    return (uint32_t)__cvta_generic_to_shared(p);
}
__device__ __forceinline__ u64 bf2f2(uint32_t w) {
    uint32_t lo, hi;
    asm("prmt.b32 %0, %1, %2, 0x1044;" : "=r"(lo) : "r"(w), "r"(0u));
    asm("prmt.b32 %0, %1, %2, 0x3244;" : "=r"(hi) : "r"(w), "r"(0u));
    u64 r;
    asm("mov.b64 %0, {%1,%2};" : "=l"(r) : "r"(lo), "r"(hi));
    return r;
}
__device__ __forceinline__ void ffma2(u64& d, u64 a, u64 b) {
    asm("fma.rn.f32x2 %0, %1, %2, %0;" : "+l"(d) : "l"(a), "l"(b));
}
__device__ __forceinline__ float sum2(u64 v) {
    float x, y;
    asm("mov.b64 {%0, %1}, %2;" : "=f"(x), "=f"(y) : "l"(v));
    return x + y;
}
__device__ __forceinline__ void lds2x64(u64& a, u64& b, uint32_t addr) {
    asm volatile("ld.shared.v2.u64 {%0,%1}, [%2];" : "=l"(a), "=l"(b) : "r"(addr));
}
__device__ __forceinline__ void st_peer_f32(uint32_t addr, uint32_t peer, float v) {
    uint32_t ra;
    asm("mapa.shared::cluster.u32 %0, %1, %2;" : "=r"(ra) : "r"(addr), "r"(peer));
    asm volatile("st.shared::cluster.f32 [%0], %1;" :: "r"(ra), "f"(v) : "memory");
}
__device__ __forceinline__ void cluster_sync_() {
    asm volatile("barrier.cluster.arrive.aligned;" ::: "memory");
    asm volatile("barrier.cluster.wait.aligned;" ::: "memory");
}
__device__ __forceinline__ float sigf(float x) { return 1.0f / (1.0f + __expf(-x)); }
__device__ __forceinline__ float tanh_f(float x) {
    return 1.0f - 2.0f / (__expf(2.0f * x) + 1.0f);
}

// h storage: per kp-row of 32 bytes: [b0k0,b0k1,b1k0,b1k1,b2k0,b2k1,b3k0,b3k1]
__device__ __forceinline__ int hidx(int j, int b) {
    return ((j >> 1) << 3) + (b << 1) + (j & 1);
}

#define PSTR 49   // part[] row stride in floats (conflict-free: 49 mod 32 = 17)

__global__ void __launch_bounds__(NTHR, 1) __cluster_dims__(2, 1, 1)
lstm_decoder_kernel(const float* __restrict__ seq,   // (B,T,1)
                    const float* __restrict__ z,     // (B,H)
                    const float* __restrict__ wih0,  // (4H,1)
                    const float* __restrict__ bih0, const float* __restrict__ bhh0,
                    const float* __restrict__ bih1, const float* __restrict__ bhh1,
                    const float* __restrict__ wout,  // (1,H)
                    const float* __restrict__ bout,  // (1,)
                    float* out) {
    __shared__ __align__(16) float hp0[2][128 * 8];   // layer0 h, ping-pong (4KB ea)
    __shared__ __align__(16) float hp1[2][128 * 8];   // layer1 h, ping-pong
    __shared__ float part[128 * PSTR];                // groups 1-3 partials
    __shared__ float pred_s[BC];
    __shared__ float wout_s[HDIM];

    const int tid  = threadIdx.x;
    const int g    = tid >> 7;       // K-quarter this thread reduces
    const int jl   = tid & 127;      // local hidden index
    const int rank = blockIdx.x & 1;
    const int peer = rank ^ 1;
    const int j    = rank * 128 + jl;
    const int b0   = (blockIdx.x >> 1) * BC;
    const int w    = tid >> 5, l = tid & 31;

    // ---- init h from z ----
    for (int idx = tid; idx < BC * HDIM; idx += NTHR) {
        int b = idx >> 8, jj = idx & 255;
        float v = z[(b0 + b) * HDIM + jj];
        hp0[0][hidx(jj, b)] = v;
        hp1[0][hidx(jj, b)] = v;
    }
    if (tid < BC) pred_s[tid] = 0.0f;
    if (tid < HDIM) wout_s[tid] = wout[tid];

    float c0[BC], c1[BC];
#pragma unroll
    for (int b = 0; b < BC; b++) {
        float v = z[(b0 + b) * HDIM + j];
        c0[b] = v;
        c1[b] = v;
    }

    // finalization constants (used by g==0 threads)
    const float bi0 = bih0[j] + bhh0[j];
    const float bf0 = bih0[256 + j] + bhh0[256 + j];
    const float bg0 = bih0[512 + j] + bhh0[512 + j];
    const float bo0 = bih0[768 + j] + bhh0[768 + j];
    const float bi1 = bih1[j] + bhh1[j];
    const float bf1 = bih1[256 + j] + bhh1[256 + j];
    const float bg1 = bih1[512 + j] + bhh1[512 + j];
    const float bo1 = bih1[768 + j] + bhh1[768 + j];
    const float wii = wih0[j], wif = wih0[256 + j], wig = wih0[512 + j], wio = wih0[768 + j];
    const float bo_out = bout[0];
    const float inv_n  = 1.0f / ((float)BTOT * (float)TSTEPS);

    const uint4* w0 = L0p + rank * (32 * 512) + tid;
    const uint4* w1 = L1p + rank * (64 * 512) + tid;

    float loss = 0.0f;
    __syncthreads();

    for (int t = 0; t < TSTEPS; t++) {
        const int cur = t & 1, nxt = cur ^ 1;

        // ================= layer 0 (K-quarter g of h0_prev) =================
        u64 acc[16];
#pragma unroll
        for (int q = 0; q < 16; q++) acc[q] = 0ull;
        {
            const uint32_t hbase = s2u(&hp0[cur][0]) + g * 1024;  // k = 64g
#pragma unroll 4
            for (int kp = 0; kp < 32; kp++) {
                uint4 wv = w0[kp * 512];
                u64 wi2 = bf2f2(wv.x), wf2 = bf2f2(wv.y);
                u64 wg2 = bf2f2(wv.z), wo2 = bf2f2(wv.w);
                u64 h01a, h01b, h23a, h23b;
                lds2x64(h01a, h01b, hbase + kp * 32);
                lds2x64(h23a, h23b, hbase + kp * 32 + 16);
                ffma2(acc[0], wi2, h01a);  ffma2(acc[1], wf2, h01a);
                ffma2(acc[2], wg2, h01a);  ffma2(acc[3], wo2, h01a);
                ffma2(acc[4], wi2, h01b);  ffma2(acc[5], wf2, h01b);
                ffma2(acc[6], wg2, h01b);  ffma2(acc[7], wo2, h01b);
                ffma2(acc[8], wi2, h23a);  ffma2(acc[9], wf2, h23a);
                ffma2(acc[10], wg2, h23a); ffma2(acc[11], wo2, h23a);
                ffma2(acc[12], wi2, h23b); ffma2(acc[13], wf2, h23b);
                ffma2(acc[14], wg2, h23b); ffma2(acc[15], wo2, h23b);
            }
        }
        if (g) {
#pragma unroll
            for (int q = 0; q < 16; q++) part[jl * PSTR + (g - 1) * 16 + q] = sum2(acc[q]);
        }
        __syncthreads();
        if (!g) {
            const uint32_t hdst = s2u(&hp0[nxt][0]);
            const float* pr = &part[jl * PSTR];
#pragma unroll
            for (int b = 0; b < BC; b++) {
                int q = b * 4;
                float p  = pred_s[b];
                float gi = sum2(acc[q + 0]) + pr[q + 0] + pr[16 + q + 0] + pr[32 + q + 0] + bi0 + p * wii;
                float gf = sum2(acc[q + 1]) + pr[q + 1] + pr[16 + q + 1] + pr[32 + q + 1] + bf0 + p * wif;
                float gg = sum2(acc[q + 2]) + pr[q + 2] + pr[16 + q + 2] + pr[32 + q + 2] + bg0 + p * wig;
                float go = sum2(acc[q + 3]) + pr[q + 3] + pr[16 + q + 3] + pr[32 + q + 3] + bo0 + p * wio;
                float cn = sigf(gf) * c0[b] + sigf(gi) * tanh_f(gg);
                c0[b] = cn;
                float hn = sigf(go) * tanh_f(cn);
                int idx = hidx(j, b);
                hp0[nxt][idx] = hn;
                st_peer_f32(hdst + idx * 4, peer, hn);
            }
        }
        cluster_sync_();

        // ===== layer 1 (g0,g1: h0_new via Wih1; g2,g3: h1_prev via Whh1) =====
#pragma unroll
        for (int q = 0; q < 16; q++) acc[q] = 0ull;
        {
            const uint32_t hbase = (g < 2)
                ? s2u(&hp0[nxt][0]) + g * 2048          // k = 128g of h0_new
                : s2u(&hp1[cur][0]) + (g - 2) * 2048;   // k = 128(g-2) of h1_prev
#pragma unroll 4
            for (int kp = 0; kp < 64; kp++) {
                uint4 wv = w1[kp * 512];
                u64 wi2 = bf2f2(wv.x), wf2 = bf2f2(wv.y);
                u64 wg2 = bf2f2(wv.z), wo2 = bf2f2(wv.w);
                u64 h01a, h01b, h23a, h23b;
                lds2x64(h01a, h01b, hbase + kp * 32);
                lds2x64(h23a, h23b, hbase + kp * 32 + 16);
                ffma2(acc[0], wi2, h01a);  ffma2(acc[1], wf2, h01a);
                ffma2(acc[2], wg2, h01a);  ffma2(acc[3], wo2, h01a);
                ffma2(acc[4], wi2, h01b);  ffma2(acc[5], wf2, h01b);
                ffma2(acc[6], wg2, h01b);  ffma2(acc[7], wo2, h01b);
                ffma2(acc[8], wi2, h23a);  ffma2(acc[9], wf2, h23a);
                ffma2(acc[10], wg2, h23a); ffma2(acc[11], wo2, h23a);
                ffma2(acc[12], wi2, h23b); ffma2(acc[13], wf2, h23b);
                ffma2(acc[14], wg2, h23b); ffma2(acc[15], wo2, h23b);
            }
        }
        if (g) {
#pragma unroll
            for (int q = 0; q < 16; q++) part[jl * PSTR + (g - 1) * 16 + q] = sum2(acc[q]);
        }
        __syncthreads();
        if (!g) {
            const uint32_t hdst = s2u(&hp1[nxt][0]);
            const float* pr = &part[jl * PSTR];
#pragma unroll
            for (int b = 0; b < BC; b++) {
                int q = b * 4;
                float gi = sum2(acc[q + 0]) + pr[q + 0] + pr[16 + q + 0] + pr[32 + q + 0] + bi1;
                float gf = sum2(acc[q + 1]) + pr[q + 1] + pr[16 + q + 1] + pr[32 + q + 1] + bf1;
                float gg = sum2(acc[q + 2]) + pr[q + 2] + pr[16 + q + 2] + pr[32 + q + 2] + bg1;
                float go = sum2(acc[q + 3]) + pr[q + 3] + pr[16 + q + 3] + pr[32 + q + 3] + bo1;
                float cn = sigf(gf) * c1[b] + sigf(gi) * tanh_f(gg);
                c1[b] = cn;
                float hn = sigf(go) * tanh_f(cn);
                int idx = hidx(j, b);
                hp1[nxt][idx] = hn;
                st_peer_f32(hdst + idx * 4, peer, hn);
            }
        }
        cluster_sync_();

        // ============ output projection + loss (warp w -> batch w) ============
        if (w < BC) {
            float s = 0.0f;
#pragma unroll
            for (int m = 0; m < 8; m++) {
                int j2 = l + (m << 5);
                s += wout_s[j2] * hp1[nxt][hidx(j2, w)];
            }
#pragma unroll
            for (int off = 16; off; off >>= 1) s += __shfl_xor_sync(0xffffffffu, s, off);
            float p = s + bo_out;
            if (l == 0) {
                pred_s[w] = p;
                if (rank == 0) {
                    float d = seq[(b0 + w) * TSTEPS + t] - p;
                    loss += d * d;
                }
            }
        }
        __syncthreads();
    }

    if (rank == 0 && w < BC && l == 0) {
        atomicAdd(out, loss * inv_n);
    }
}

extern "C" void kernel_launch(void* const* d_in, const int* in_sizes, int n_in,
                              void* d_out, int out_size) {
    const float* seq  = (const float*)d_in[0];
    const float* z    = (const float*)d_in[1];
    // d_in[2] = lengths (all == T; unused by the math)
    const float* wih0 = (const float*)d_in[3];
    const float* whh0 = (const float*)d_in[4];
    const float* bih0 = (const float*)d_in[5];
    const float* bhh0 = (const float*)d_in[6];
    const float* wih1 = (const float*)d_in[7];
    const float* whh1 = (const float*)d_in[8];
    const float* bih1 = (const float*)d_in[9];
    const float* bhh1 = (const float*)d_in[10];
    const float* wout = (const float*)d_in[11];
    const float* bout = (const float*)d_in[12];
    float* out = (float*)d_out;

    prep_kernel<<<384, 256>>>(whh0, wih1, whh1, out);
    lstm_decoder_kernel<<<NCTA, NTHR>>>(seq, z, wih0, bih0, bhh0,
                                        bih1, bhh1, wout, bout, out);
}